// round 3
// baseline (speedup 1.0000x reference)
#include <cuda_runtime.h>
#include <cuda_fp16.h>
#include <cstdint>
#include <cstddef>

#define DI __device__ __forceinline__

// ---------------- problem constants ----------------
constexpr int BB = 8, CI = 512, CO = 512, KW = 5, LL = 4096;

// ---------------- GEMM tiling ----------------
constexpr int BM = 128, BN = 128, BK = 64;      // halfs
constexpr int NIT = (CI / BK) * KW;             // 40 k-iterations
constexpr int TILE_B = 16384;                   // 128 rows x 128B (both A and B tiles)
constexpr int STAGE_B = 2 * TILE_B;             // 32 KB
constexpr int NSTAGE = 3;
constexpr int GEMM_SMEM = NSTAGE * STAGE_B;     // 96 KB

// ---------------- device scratch (no allocations allowed) ----------------
// B tiles: [b][k][lT(32)][ic(8)], each 128x128B swizzled, contiguous 16KB
__device__ __half g_B[(size_t)BB * KW * 32 * 8 * 8192];
// W tiles: [k][oT(4)][ic(8)], each 128x128B swizzled, contiguous 16KB
__device__ __half g_W[(size_t)KW * 4 * 8 * 8192];
__device__ float  g_avg[BB * CI];
__device__ float  g_ka[BB * KW];
__device__ float  g_scale[BB * CO];

// ---------------- helpers ----------------
DI uint32_t smem_u32(const void* p) {
    uint32_t a;
    asm("{ .reg .u64 t; cvta.to.shared.u64 t, %1; cvt.u32.u64 %0, t; }" : "=r"(a) : "l"(p));
    return a;
}
DI uint32_t swz(uint32_t off) { return off ^ ((off >> 3) & 0x70); }
DI void cp16(uint32_t dst, const void* src) {
    asm volatile("cp.async.cg.shared.global [%0], [%1], 16;" :: "r"(dst), "l"(src) : "memory");
}
DI void cp_commit() { asm volatile("cp.async.commit_group;" ::: "memory"); }
template <int N> DI void cp_wait() { asm volatile("cp.async.wait_group %0;" :: "n"(N) : "memory"); }

DI void ldmx4(uint32_t& r0, uint32_t& r1, uint32_t& r2, uint32_t& r3, uint32_t a) {
    asm volatile("ldmatrix.sync.aligned.m8n8.x4.shared.b16 {%0,%1,%2,%3}, [%4];"
                 : "=r"(r0), "=r"(r1), "=r"(r2), "=r"(r3) : "r"(a));
}
DI void ldmx2(uint32_t& r0, uint32_t& r1, uint32_t a) {
    asm volatile("ldmatrix.sync.aligned.m8n8.x2.shared.b16 {%0,%1}, [%2];"
                 : "=r"(r0), "=r"(r1) : "r"(a));
}
DI void mma16816(float* c, const uint32_t* a, const uint32_t* b) {
    asm volatile(
        "mma.sync.aligned.m16n8k16.row.col.f32.f16.f16.f32 "
        "{%0,%1,%2,%3}, {%4,%5,%6,%7}, {%8,%9}, {%0,%1,%2,%3};"
        : "+f"(c[0]), "+f"(c[1]), "+f"(c[2]), "+f"(c[3])
        : "r"(a[0]), "r"(a[1]), "r"(a[2]), "r"(a[3]), "r"(b[0]), "r"(b[1]));
}

// ---------------- kernel 1: per-(b,c) mean over L ----------------
__global__ void k_avg(const float* __restrict__ x) {
    int row = blockIdx.x;  // b*CI + c
    const float4* p = (const float4*)(x + (size_t)row * LL);
    float s = 0.f;
#pragma unroll
    for (int q = 0; q < 4; ++q) {
        float4 v = p[threadIdx.x + q * 256];
        s += (v.x + v.y) + (v.z + v.w);
    }
#pragma unroll
    for (int o = 16; o; o >>= 1) s += __shfl_xor_sync(0xFFFFFFFFu, s, o);
    __shared__ float ws[8];
    if ((threadIdx.x & 31) == 0) ws[threadIdx.x >> 5] = s;
    __syncthreads();
    if (threadIdx.x == 0) {
        float t = 0.f;
#pragma unroll
        for (int w = 0; w < 8; ++w) t += ws[w];
        g_avg[row] = t * (1.f / (float)LL);
    }
}

// ---------------- kernel 2: attention branches ----------------
__global__ void k_att(
    const float* ka_w1, const float* ka_b1, const float* ka_w2, const float* ka_b2,
    const float* sa_w1, const float* sa_b1, const float* sa_w2, const float* sa_b2,
    const float* ia_w1, const float* ia_b1, const float* ia_w2, const float* ia_b2,
    const float* oa_w1, const float* oa_b1, const float* oa_w2, const float* oa_b2) {
    __shared__ float avgs[CI], h[128], iaa[CO], oaa[CO], sav;
    int b = blockIdx.x, t = threadIdx.x;
#pragma unroll
    for (int q = 0; q < 4; ++q) avgs[t + q * 128] = g_avg[b * CI + t + q * 128];
    __syncthreads();
#pragma unroll 1
    for (int br = 0; br < 4; ++br) {
        const float *w1, *b1, *w2, *b2; int od;
        if (br == 0) { w1 = ka_w1; b1 = ka_b1; w2 = ka_w2; b2 = ka_b2; od = KW; }
        else if (br == 1) { w1 = sa_w1; b1 = sa_b1; w2 = sa_w2; b2 = sa_b2; od = 1; }
        else if (br == 2) { w1 = ia_w1; b1 = ia_b1; w2 = ia_w2; b2 = ia_b2; od = CI; }
        else { w1 = oa_w1; b1 = oa_b1; w2 = oa_w2; b2 = oa_b2; od = CO; }
        float s = b1[t];
        const float* wr = w1 + (size_t)t * CI;
        for (int u = 0; u < CI; ++u) s += avgs[u] * wr[u];
        h[t] = fmaxf(s, 0.f);
        __syncthreads();
        for (int idx = t; idx < od; idx += 128) {
            float s2 = b2[idx];
            const float* w2r = w2 + (size_t)idx * 128;
#pragma unroll 8
            for (int r = 0; r < 128; ++r) s2 += h[r] * w2r[r];
            float sg = 1.f / (1.f + expf(-s2));
            if (br == 0) g_ka[b * KW + idx] = sg;
            else if (br == 1) sav = sg;
            else if (br == 2) iaa[idx] = sg;
            else oaa[idx] = sg;
        }
        __syncthreads();
    }
    float sv = sav;
#pragma unroll
    for (int q = 0; q < 4; ++q) {
        int o = t + q * 128;
        g_scale[b * CO + o] = sv * iaa[o] * oaa[o];
    }
}

// ---------------- kernel 3: swizzle weight tiles (fp16) ----------------
__global__ void k_prepW(const float* __restrict__ w) {
    int bx = blockIdx.x;                 // (k*4+oT)*8+ic, 160 blocks
    int k = bx >> 5, oT = (bx >> 3) & 3, ic = bx & 7;
    int o = oT * 128 + threadIdx.x;      // 128 threads = rows
    char* tile = (char*)g_W + (size_t)bx * TILE_B;
#pragma unroll 8
    for (int j2 = 0; j2 < 32; ++j2) {
        int i = ic * 64 + 2 * j2;
        float v0 = w[((size_t)o * CI + i) * KW + k];
        float v1 = w[((size_t)o * CI + i + 1) * KW + k];
        __half2 hv = __floats2half2_rn(v0, v1);
        *(uint32_t*)(tile + swz((uint32_t)threadIdx.x * 128 + j2 * 4)) = *(uint32_t*)&hv;
    }
}

// ---------------- kernel 4: shifted, ka-scaled, swizzled x tiles ----------------
__global__ void k_prepB(const float* __restrict__ x) {
    extern __shared__ float xs[];        // [64][133] padded: i-row, l-col
    int bx = blockIdx.x;                 // (b*32+lT)*8+ic, 2048 blocks
    int b = bx >> 8, lT = (bx >> 3) & 31, ic = bx & 7;
    int tid = threadIdx.x;               // 256 threads
    int lbase = lT * 128 - 2;            // need l in [lbase, lbase+132)
    for (int e = tid; e < 64 * 132; e += 256) {
        int r = e / 132, off = e - r * 132;
        int lg = lbase + off;
        float v = 0.f;
        if (lg >= 0 && lg < LL)
            v = x[((size_t)(b * CI + ic * 64 + r)) * LL + lg];
        xs[r * 133 + off] = v;
    }
    __syncthreads();
#pragma unroll 1
    for (int k = 0; k < KW; ++k) {
        float kaf = g_ka[b * KW + k];
        char* tile = (char*)g_B +
            (((size_t)(b * KW + k) * 32 + lT) * 8 + ic) * (size_t)TILE_B;
#pragma unroll
        for (int q = 0; q < 4; ++q) {
            int c = tid + q * 256;             // 1024 chunks: 128 rows x 8
            int l = c >> 3, j = c & 7;
            uint32_t u[4];
#pragma unroll
            for (int p = 0; p < 4; ++p) {
                float a0 = kaf * xs[(j * 8 + 2 * p) * 133 + l + k];
                float a1 = kaf * xs[(j * 8 + 2 * p + 1) * 133 + l + k];
                __half2 hv = __floats2half2_rn(a0, a1);
                u[p] = *(uint32_t*)&hv;
            }
            *(uint4*)(tile + swz((uint32_t)l * 128 + j * 16)) =
                make_uint4(u[0], u[1], u[2], u[3]);
        }
    }
}

// ---------------- kernel 5: HMMA GEMM + fused epilogue ----------------
__global__ void __launch_bounds__(256, 2)
k_gemm(const float* __restrict__ bias, float* __restrict__ out) {
    extern __shared__ char sm[];
    uint32_t sbase = smem_u32(sm);
    int tid = threadIdx.x, lane = tid & 31, wid = tid >> 5;
    int bx = blockIdx.x;
    int oT = bx & 3, lT = (bx >> 2) & 31, b = bx >> 7;
    int wm = (wid & 1) * 64, wn = (wid >> 1) * 32;

    const char* wb = (const char*)g_W;
    const char* bb = (const char*)g_B;

    // cp.async stage fill: 8 x 16B per thread
    auto issue = [&](int j, int s) {
        int kw = j >> 3, ic = j & 7;
        const char* sA = wb + ((size_t)((kw * 4 + oT) * 8 + ic)) * TILE_B;
        const char* sB = bb + (((size_t)(b * KW + kw) * 32 + lT) * 8 + ic) * (size_t)TILE_B;
        uint32_t dA = sbase + s * STAGE_B;
        uint32_t dB = dA + TILE_B;
#pragma unroll
        for (int q = 0; q < 4; ++q) {
            int c = (tid + q * 256) * 16;
            cp16(dA + c, sA + c);
        }
#pragma unroll
        for (int q = 0; q < 4; ++q) {
            int c = (tid + q * 256) * 16;
            cp16(dB + c, sB + c);
        }
    };

    float acc[4][4][4];
#pragma unroll
    for (int mi = 0; mi < 4; ++mi)
#pragma unroll
        for (int ni = 0; ni < 4; ++ni)
#pragma unroll
            for (int r = 0; r < 4; ++r) acc[mi][ni][r] = 0.f;

    // ldmatrix per-lane address components
    int rowA = (lane & 7) + 8 * ((lane >> 3) & 1);
    int colA = (lane >> 4) * 16;
    int rowB = lane & 7;
    int colB = ((lane >> 3) & 1) * 16;

    issue(0, 0); cp_commit();
    issue(1, 1); cp_commit();

#pragma unroll 1
    for (int it = 0; it < NIT; ++it) {
        int j2 = it + 2;
        if (j2 < NIT) issue(j2, j2 % 3);
        cp_commit();
        cp_wait<2>();
        __syncthreads();

        uint32_t sA = sbase + (it % 3) * STAGE_B;
        uint32_t sB = sA + TILE_B;
#pragma unroll
        for (int ks = 0; ks < 4; ++ks) {
            uint32_t afr[4][4], bfr[4][2];
#pragma unroll
            for (int mi = 0; mi < 4; ++mi)
                ldmx4(afr[mi][0], afr[mi][1], afr[mi][2], afr[mi][3],
                      sA + swz((uint32_t)(wm + mi * 16 + rowA) * 128 + ks * 32 + colA));
#pragma unroll
            for (int ni = 0; ni < 4; ++ni)
                ldmx2(bfr[ni][0], bfr[ni][1],
                      sB + swz((uint32_t)(wn + ni * 8 + rowB) * 128 + ks * 32 + colB));
#pragma unroll
            for (int mi = 0; mi < 4; ++mi)
#pragma unroll
                for (int ni = 0; ni < 4; ++ni)
                    mma16816(acc[mi][ni], afr[mi], bfr[ni]);
        }
        __syncthreads();
    }

    // epilogue: scale*acc + bias, direct stores (32B-sector complete)
    int r0 = wm + (lane >> 2);
    float scb[4][2], bib[4][2];
#pragma unroll
    for (int mi = 0; mi < 4; ++mi) {
        int o0 = oT * 128 + r0 + mi * 16;
        scb[mi][0] = g_scale[b * CO + o0];
        scb[mi][1] = g_scale[b * CO + o0 + 8];
        bib[mi][0] = bias[o0];
        bib[mi][1] = bias[o0 + 8];
    }
    float* ob = out + ((size_t)(b * CO + oT * 128)) * LL + lT * 128;
#pragma unroll
    for (int mi = 0; mi < 4; ++mi) {
#pragma unroll
        for (int ni = 0; ni < 4; ++ni) {
            int rr = r0 + mi * 16;
            int cc = wn + ni * 8 + (lane & 3) * 2;
            float2 v0 = make_float2(scb[mi][0] * acc[mi][ni][0] + bib[mi][0],
                                    scb[mi][0] * acc[mi][ni][1] + bib[mi][0]);
            float2 v1 = make_float2(scb[mi][1] * acc[mi][ni][2] + bib[mi][1],
                                    scb[mi][1] * acc[mi][ni][3] + bib[mi][1]);
            *(float2*)(ob + (size_t)rr * LL + cc) = v0;
            *(float2*)(ob + (size_t)(rr + 8) * LL + cc) = v1;
        }
    }
}

// ---------------- launch ----------------
extern "C" void kernel_launch(void* const* d_in, const int* in_sizes, int n_in,
                              void* d_out, int out_size) {
    const float* x      = (const float*)d_in[0];
    const float* weight = (const float*)d_in[1];
    const float* bias   = (const float*)d_in[2];
    const float* ka_w1 = (const float*)d_in[3],  *ka_b1 = (const float*)d_in[4];
    const float* ka_w2 = (const float*)d_in[5],  *ka_b2 = (const float*)d_in[6];
    const float* sa_w1 = (const float*)d_in[7],  *sa_b1 = (const float*)d_in[8];
    const float* sa_w2 = (const float*)d_in[9],  *sa_b2 = (const float*)d_in[10];
    const float* ia_w1 = (const float*)d_in[11], *ia_b1 = (const float*)d_in[12];
    const float* ia_w2 = (const float*)d_in[13], *ia_b2 = (const float*)d_in[14];
    const float* oa_w1 = (const float*)d_in[15], *oa_b1 = (const float*)d_in[16];
    const float* oa_w2 = (const float*)d_in[17], *oa_b2 = (const float*)d_in[18];
    float* out = (float*)d_out;

    cudaFuncSetAttribute(k_gemm, cudaFuncAttributeMaxDynamicSharedMemorySize, GEMM_SMEM);

    k_avg<<<BB * CI, 256>>>(x);
    k_att<<<BB, 128>>>(ka_w1, ka_b1, ka_w2, ka_b2,
                       sa_w1, sa_b1, sa_w2, sa_b2,
                       ia_w1, ia_b1, ia_w2, ia_b2,
                       oa_w1, oa_b1, oa_w2, oa_b2);
    k_prepW<<<KW * 4 * 8, 128>>>(weight);
    k_prepB<<<BB * 32 * 8, 256, 64 * 133 * 4>>>(x);
    k_gemm<<<BB * 32 * 4, 256, GEMM_SMEM>>>(bias, out);
}